// round 9
// baseline (speedup 1.0000x reference)
#include <cuda_runtime.h>
#include <cuda_fp16.h>
#include <cstdint>
#include <cstddef>

#define NROWS  8192
#define INF    1024
#define OUTF   1024
#define KDIM   9216
#define KSTEP  96
#define NIT    96           // KDIM / 96
#define ROWB   208          // 192 data bytes + 16 pad
#define A_SZ   (128 * ROWB)         // 26624
#define B_SZ   (128 * ROWB)         // 26624
#define STAGE_SZ (A_SZ + B_SZ)      // 53248
#define SMEM_BYTES (2 * STAGE_SZ)   // 106496
#define NTHR   256

// ---------------- scratch (device globals) ----------------------------------
__device__ __align__(1024) __half g_G[(size_t)NROWS * KDIM];
__device__ __align__(1024) __half g_W[(size_t)OUTF * KDIM];

// ---------------- helpers ----------------------------------------------------
static __device__ __forceinline__ uint32_t smem_u32(const void* p) {
    uint32_t a;
    asm("{ .reg .u64 t; cvta.to.shared.u64 t, %1; cvt.u32.u64 %0, t; }"
        : "=r"(a) : "l"(p));
    return a;
}
static __device__ __forceinline__ void cp16(uint32_t s, const void* g) {
    asm volatile("cp.async.cg.shared.global [%0], [%1], 16;" :: "r"(s), "l"(g));
}
static __device__ __forceinline__ void cp_commit() {
    asm volatile("cp.async.commit_group;" ::: "memory");
}
static __device__ __forceinline__ void cp_wait0() {
    asm volatile("cp.async.wait_group 0;" ::: "memory");
}
#define LDSM4(r, adr) \
    asm volatile("ldmatrix.sync.aligned.m8n8.x4.shared.b16 {%0,%1,%2,%3}, [%4];" \
                 : "=r"((r)[0]), "=r"((r)[1]), "=r"((r)[2]), "=r"((r)[3]) \
                 : "r"(adr))
static __device__ __forceinline__ void mma16816(
    float* c, const uint32_t* a, uint32_t b0, uint32_t b1)
{
    asm volatile(
        "mma.sync.aligned.m16n8k16.row.col.f32.f16.f16.f32 "
        "{%0,%1,%2,%3}, {%4,%5,%6,%7}, {%8,%9}, {%0,%1,%2,%3};"
        : "+f"(c[0]), "+f"(c[1]), "+f"(c[2]), "+f"(c[3])
        : "r"(a[0]), "r"(a[1]), "r"(a[2]), "r"(a[3]), "r"(b0), "r"(b1));
}
static __device__ __forceinline__ uint32_t pack_h2(float a, float b) {
    __half2 t = __floats2half2_rn(a, b);
    return *reinterpret_cast<uint32_t*>(&t);
}

// ---------------- kernel 1: prep (W convert + features), merged --------------
__global__ void prep_kernel(const float* __restrict__ spline_w,
                            const float* __restrict__ base_w,
                            const float* __restrict__ x,
                            const float* __restrict__ gamma,
                            const float* __restrict__ beta)
{
    const int tid = threadIdx.x;            // 256 threads

    if (blockIdx.x < OUTF) {
        // ---- W row: convert [spline_w | base_w] -> fp16 ----
        const int o = blockIdx.x;
        const size_t rb = (size_t)o * KDIM;
        for (int k = tid; k < KDIM; k += 256) {
            float v = (k < 8192) ? spline_w[(size_t)o * 8192 + k]
                                 : base_w[(size_t)o * 1024 + (k - 8192)];
            g_W[rb + k] = __float2half_rn(v);
        }
        return;
    }

    // ---- G row: LayerNorm + RBF + silu ----
    const int row = blockIdx.x - OUTF;
    const int lane = tid & 31, wid = tid >> 5;

    const float4 v = reinterpret_cast<const float4*>(x + (size_t)row * INF)[tid];
    float s  = v.x + v.y + v.z + v.w;
    float sq = v.x * v.x + v.y * v.y + v.z * v.z + v.w * v.w;
#pragma unroll
    for (int o = 16; o > 0; o >>= 1) {
        s  += __shfl_xor_sync(0xFFFFFFFFu, s,  o);
        sq += __shfl_xor_sync(0xFFFFFFFFu, sq, o);
    }
    __shared__ float rs[8], rq[8], s_mu, s_rstd;
    if (lane == 0) { rs[wid] = s; rq[wid] = sq; }
    __syncthreads();
    if (tid == 0) {
        float S = 0.f, Q = 0.f;
#pragma unroll
        for (int i = 0; i < 8; i++) { S += rs[i]; Q += rq[i]; }
        float mu = S * (1.0f / INF);
        float var = Q * (1.0f / INF) - mu * mu;
        s_mu = mu;
        s_rstd = rsqrtf(var + 1e-5f);
    }
    __syncthreads();
    const float mu = s_mu, rstd = s_rstd;

    __half* gh = g_G + (size_t)row * KDIM;
    const float xv4[4] = { v.x, v.y, v.z, v.w };

#pragma unroll
    for (int e = 0; e < 4; e++) {
        const int in = tid * 4 + e;
        const float xv = xv4[e];
        const float xn = (xv - mu) * rstd * gamma[in] + beta[in];
        const float t0 = (xn + 2.0f) * 1.75f;   // (xn - grid_g)/DENOM = t0 - g
        float b[8];
#pragma unroll
        for (int g = 0; g < 8; g++) {
            float d = t0 - (float)g;
            b[g] = __expf(-d * d);
        }
        uint4 H;
        H.x = pack_h2(b[0], b[1]); H.y = pack_h2(b[2], b[3]);
        H.z = pack_h2(b[4], b[5]); H.w = pack_h2(b[6], b[7]);
        *reinterpret_cast<uint4*>(gh + (size_t)in * 8) = H;

        float sl = xv / (1.0f + __expf(-xv));     // silu(x), original x
        gh[8192 + in] = __float2half_rn(sl);
    }
}

// ---------------- kernel 2: mma.sync GEMM  Y = G W^T + b ---------------------
// CTA 128x128, 8 warps of 32x64 (4m x 2n), K-step 96, 2-stage cp.async,
// 2 CTAs / SM.
__global__ void __launch_bounds__(NTHR, 2)
gemm_kernel(const float* __restrict__ bias, float* __restrict__ out)
{
    extern __shared__ __align__(128) char smem[];
    const uint32_t sb = smem_u32(smem);
    const int tid  = threadIdx.x;
    const int lane = tid & 31;
    const int wid  = tid >> 5;
    const int warp_m = wid & 3;     // 4 x 32 rows
    const int warp_n = wid >> 2;    // 2 x 64 cols
    const int n0 = blockIdx.x * 128;
    const int m0 = blockIdx.y * 128;

    // ---- cp.async per-thread geometry (16B chunks, 12 per 192B row) ----
    const __half* baseG = g_G;
    const __half* baseW = g_W;
    uint32_t dA[6], gA[6];
#pragma unroll
    for (int j = 0; j < 6; j++) {                 // A: 1536 chunks / 256 thr
        int c = tid + NTHR * j;
        int r = c / 12, sgs = c % 12;
        dA[j] = (uint32_t)(r * ROWB + sgs * 16);
        gA[j] = (uint32_t)((m0 + r) * KDIM + sgs * 8);
    }
    uint32_t dB[6], gB[6];
#pragma unroll
    for (int j = 0; j < 6; j++) {                 // B: 1536 chunks / 256 thr
        int c = tid + NTHR * j;
        int r = c / 12, sgs = c % 12;
        dB[j] = (uint32_t)(A_SZ + r * ROWB + sgs * 16);
        gB[j] = (uint32_t)((n0 + r) * KDIM + sgs * 8);
    }

    auto load_stage = [&](int it, int stg) {
        const uint32_t kcol = (uint32_t)it * KSTEP;
        const uint32_t st = sb + (uint32_t)(stg * STAGE_SZ);
#pragma unroll
        for (int j = 0; j < 6; j++) cp16(st + dA[j], baseG + gA[j] + kcol);
#pragma unroll
        for (int j = 0; j < 6; j++) cp16(st + dB[j], baseW + gB[j] + kcol);
    };

    // ---- ldmatrix per-thread lane offsets ----
    const uint32_t aLane = (uint32_t)((warp_m * 32 + ((lane >> 3) & 1) * 8 + (lane & 7)) * ROWB
                                      + (lane >> 4) * 16);
    const uint32_t bLane = (uint32_t)(A_SZ
                                      + (warp_n * 64 + ((lane >> 4) & 1) * 8 + (lane & 7)) * ROWB
                                      + ((lane >> 3) & 1) * 16);

    float acc[64];
#pragma unroll
    for (int i = 0; i < 64; i++) acc[i] = 0.0f;

    // prologue: fill stage 0
    load_stage(0, 0); cp_commit();

    for (int it = 0; it < NIT; it++) {
        cp_wait0();                 // stage(it) resident
        __syncthreads();
        if (it + 1 < NIT) load_stage(it + 1, (it + 1) & 1);
        cp_commit();

        const uint32_t st = sb + (uint32_t)((it & 1) * STAGE_SZ);
#pragma unroll
        for (int kh = 0; kh < 6; kh++) {
            uint32_t a[2][4], b[4][4];
#pragma unroll
            for (int ms = 0; ms < 2; ms++)
                LDSM4(a[ms], st + aLane + (uint32_t)(ms * 16 * ROWB) + (uint32_t)(kh * 32));
#pragma unroll
            for (int p = 0; p < 4; p++)
                LDSM4(b[p], st + bLane + (uint32_t)(p * 16 * ROWB) + (uint32_t)(kh * 32));
#pragma unroll
            for (int ms = 0; ms < 2; ms++) {
#pragma unroll
                for (int p = 0; p < 4; p++) {
                    mma16816(acc + (ms * 8 + 2 * p) * 4,     a[ms], b[p][0], b[p][1]);
                    mma16816(acc + (ms * 8 + 2 * p + 1) * 4, a[ms], b[p][2], b[p][3]);
                }
            }
        }
    }

    // ---- epilogue: add bias, store fp32 ----
    const int rbase = m0 + warp_m * 32 + (lane >> 2);
    const int cbase = n0 + warp_n * 64 + (lane & 3) * 2;
#pragma unroll
    for (int ms = 0; ms < 2; ms++) {
#pragma unroll
        for (int ns = 0; ns < 8; ns++) {
            const float* c = acc + (ms * 8 + ns) * 4;
            const int col = cbase + ns * 8;
            const float2 bb = *reinterpret_cast<const float2*>(bias + col);
            const int r0 = rbase + ms * 16;
            float2 o0 = { c[0] + bb.x, c[1] + bb.y };
            float2 o1 = { c[2] + bb.x, c[3] + bb.y };
            *reinterpret_cast<float2*>(out + (size_t)r0 * OUTF + col) = o0;
            *reinterpret_cast<float2*>(out + (size_t)(r0 + 8) * OUTF + col) = o1;
        }
    }
}

// ---------------- launch -----------------------------------------------------
extern "C" void kernel_launch(void* const* d_in, const int* in_sizes, int n_in,
                              void* d_out, int out_size)
{
    (void)in_sizes; (void)n_in; (void)out_size;
    const float* x        = (const float*)d_in[0];
    const float* ln_gamma = (const float*)d_in[1];
    const float* ln_beta  = (const float*)d_in[2];
    const float* spline_w = (const float*)d_in[3];
    const float* base_w   = (const float*)d_in[4];
    const float* base_b   = (const float*)d_in[5];
    float* out = (float*)d_out;

    cudaFuncSetAttribute(gemm_kernel, cudaFuncAttributeMaxDynamicSharedMemorySize,
                         SMEM_BYTES);

    prep_kernel<<<OUTF + NROWS, 256>>>(spline_w, base_w, x, ln_gamma, ln_beta);
    gemm_kernel<<<dim3(8, 64), NTHR, SMEM_BYTES>>>(base_b, out);
}

// round 10
// speedup vs baseline: 1.0460x; 1.0460x over previous
#include <cuda_runtime.h>
#include <cuda_fp16.h>
#include <cstdint>
#include <cstddef>

#define NROWS  8192
#define INF    1024
#define OUTF   1024
#define KDIM   9216
#define KSTEP  64
#define NIT    144          // KDIM / 64
#define STAGES 3
#define ROWB   144          // 128 data bytes + 16 pad
#define A_SZ   (128 * ROWB)         // 18432
#define B_SZ   (128 * ROWB)         // 18432
#define STAGE_SZ (A_SZ + B_SZ)      // 36864
#define SMEM_BYTES (STAGES * STAGE_SZ)   // 110592
#define NTHR   256

// ---------------- scratch (device globals) ----------------------------------
__device__ __align__(1024) __half g_G[(size_t)NROWS * KDIM];
__device__ __align__(1024) __half g_W[(size_t)OUTF * KDIM];

// ---------------- helpers ----------------------------------------------------
static __device__ __forceinline__ uint32_t smem_u32(const void* p) {
    uint32_t a;
    asm("{ .reg .u64 t; cvta.to.shared.u64 t, %1; cvt.u32.u64 %0, t; }"
        : "=r"(a) : "l"(p));
    return a;
}
static __device__ __forceinline__ void cp16(uint32_t s, const void* g) {
    asm volatile("cp.async.cg.shared.global [%0], [%1], 16;" :: "r"(s), "l"(g));
}
static __device__ __forceinline__ void cp_commit() {
    asm volatile("cp.async.commit_group;" ::: "memory");
}
static __device__ __forceinline__ void cp_wait1() {
    asm volatile("cp.async.wait_group 1;" ::: "memory");
}
#define LDSM4(r, adr) \
    asm volatile("ldmatrix.sync.aligned.m8n8.x4.shared.b16 {%0,%1,%2,%3}, [%4];" \
                 : "=r"((r)[0]), "=r"((r)[1]), "=r"((r)[2]), "=r"((r)[3]) \
                 : "r"(adr))
static __device__ __forceinline__ void mma16816(
    float* c, const uint32_t* a, uint32_t b0, uint32_t b1)
{
    asm volatile(
        "mma.sync.aligned.m16n8k16.row.col.f32.f16.f16.f32 "
        "{%0,%1,%2,%3}, {%4,%5,%6,%7}, {%8,%9}, {%0,%1,%2,%3};"
        : "+f"(c[0]), "+f"(c[1]), "+f"(c[2]), "+f"(c[3])
        : "r"(a[0]), "r"(a[1]), "r"(a[2]), "r"(a[3]), "r"(b0), "r"(b1));
}
static __device__ __forceinline__ uint32_t pack_h2(float a, float b) {
    __half2 t = __floats2half2_rn(a, b);
    return *reinterpret_cast<uint32_t*>(&t);
}

// ---------------- kernel 1: prep (W convert + features), merged --------------
__global__ void prep_kernel(const float* __restrict__ spline_w,
                            const float* __restrict__ base_w,
                            const float* __restrict__ x,
                            const float* __restrict__ gamma,
                            const float* __restrict__ beta)
{
    const int tid = threadIdx.x;            // 256 threads

    if (blockIdx.x < OUTF) {
        // ---- W row: convert [spline_w | base_w] -> fp16 ----
        const int o = blockIdx.x;
        const size_t rb = (size_t)o * KDIM;
        for (int k = tid; k < KDIM; k += 256) {
            float v = (k < 8192) ? spline_w[(size_t)o * 8192 + k]
                                 : base_w[(size_t)o * 1024 + (k - 8192)];
            g_W[rb + k] = __float2half_rn(v);
        }
        return;
    }

    // ---- G row: LayerNorm + RBF + silu ----
    const int row = blockIdx.x - OUTF;
    const int lane = tid & 31, wid = tid >> 5;

    const float4 v = reinterpret_cast<const float4*>(x + (size_t)row * INF)[tid];
    float s  = v.x + v.y + v.z + v.w;
    float sq = v.x * v.x + v.y * v.y + v.z * v.z + v.w * v.w;
#pragma unroll
    for (int o = 16; o > 0; o >>= 1) {
        s  += __shfl_xor_sync(0xFFFFFFFFu, s,  o);
        sq += __shfl_xor_sync(0xFFFFFFFFu, sq, o);
    }
    __shared__ float rs[8], rq[8], s_mu, s_rstd;
    if (lane == 0) { rs[wid] = s; rq[wid] = sq; }
    __syncthreads();
    if (tid == 0) {
        float S = 0.f, Q = 0.f;
#pragma unroll
        for (int i = 0; i < 8; i++) { S += rs[i]; Q += rq[i]; }
        float mu = S * (1.0f / INF);
        float var = Q * (1.0f / INF) - mu * mu;
        s_mu = mu;
        s_rstd = rsqrtf(var + 1e-5f);
    }
    __syncthreads();
    const float mu = s_mu, rstd = s_rstd;

    __half* gh = g_G + (size_t)row * KDIM;
    const float xv4[4] = { v.x, v.y, v.z, v.w };

#pragma unroll
    for (int e = 0; e < 4; e++) {
        const int in = tid * 4 + e;
        const float xv = xv4[e];
        const float xn = (xv - mu) * rstd * gamma[in] + beta[in];
        const float t0 = (xn + 2.0f) * 1.75f;   // (xn - grid_g)/DENOM = t0 - g
        float b[8];
#pragma unroll
        for (int g = 0; g < 8; g++) {
            float d = t0 - (float)g;
            b[g] = __expf(-d * d);
        }
        uint4 H;
        H.x = pack_h2(b[0], b[1]); H.y = pack_h2(b[2], b[3]);
        H.z = pack_h2(b[4], b[5]); H.w = pack_h2(b[6], b[7]);
        *reinterpret_cast<uint4*>(gh + (size_t)in * 8) = H;

        float sl = xv / (1.0f + __expf(-xv));     // silu(x), original x
        gh[8192 + in] = __float2half_rn(sl);
    }
}

// ---------------- kernel 2: mma.sync GEMM  Y = G W^T + b ---------------------
// CTA 128x128, 8 warps of 32x64 (4m x 2n), K-step 64, 3-stage cp.async,
// 2 CTAs / SM, per-warp kh rotation to break the post-barrier convoy.
__global__ void __launch_bounds__(NTHR, 2)
gemm_kernel(const float* __restrict__ bias, float* __restrict__ out)
{
    extern __shared__ __align__(128) char smem[];
    const uint32_t sb = smem_u32(smem);
    const int tid  = threadIdx.x;
    const int lane = tid & 31;
    const int wid  = tid >> 5;
    const int warp_m = wid & 3;     // 4 x 32 rows
    const int warp_n = wid >> 2;    // 2 x 64 cols
    const int n0 = blockIdx.x * 128;
    const int m0 = blockIdx.y * 128;

    // ---- cp.async per-thread geometry (16B chunks, 8 per 128B row) ----
    const __half* baseG = g_G;
    const __half* baseW = g_W;
    uint32_t dA[4], gA[4];
#pragma unroll
    for (int j = 0; j < 4; j++) {                 // A: 1024 chunks / 256 thr
        int c = tid + NTHR * j;
        int r = c >> 3, sgs = c & 7;
        dA[j] = (uint32_t)(r * ROWB + sgs * 16);
        gA[j] = (uint32_t)((m0 + r) * KDIM + sgs * 8);
    }
    uint32_t dB[4], gB[4];
#pragma unroll
    for (int j = 0; j < 4; j++) {                 // B: 1024 chunks / 256 thr
        int c = tid + NTHR * j;
        int r = c >> 3, sgs = c & 7;
        dB[j] = (uint32_t)(A_SZ + r * ROWB + sgs * 16);
        gB[j] = (uint32_t)((n0 + r) * KDIM + sgs * 8);
    }

    auto load_stage = [&](int it, int stg) {
        const uint32_t kcol = (uint32_t)it * KSTEP;
        const uint32_t st = sb + (uint32_t)(stg * STAGE_SZ);
#pragma unroll
        for (int j = 0; j < 4; j++) cp16(st + dA[j], baseG + gA[j] + kcol);
#pragma unroll
        for (int j = 0; j < 4; j++) cp16(st + dB[j], baseW + gB[j] + kcol);
    };

    // ---- ldmatrix per-thread lane offsets ----
    const uint32_t aLane = (uint32_t)((warp_m * 32 + ((lane >> 3) & 1) * 8 + (lane & 7)) * ROWB
                                      + (lane >> 4) * 16);
    const uint32_t bLane = (uint32_t)(A_SZ
                                      + (warp_n * 64 + ((lane >> 4) & 1) * 8 + (lane & 7)) * ROWB
                                      + ((lane >> 3) & 1) * 16);

    const int kh0 = wid & 3;        // per-warp K-half rotation start

    float acc[64];
#pragma unroll
    for (int i = 0; i < 64; i++) acc[i] = 0.0f;

    // prologue: fill 2 stages
    load_stage(0, 0); cp_commit();
    load_stage(1, 1); cp_commit();

    int stg = 0;
    for (int it = 0; it < NIT; it++) {
        cp_wait1();                 // stage(it) resident
        __syncthreads();
        const int stg2 = (stg + 2 >= STAGES) ? stg - 1 : stg + 2;
        if (it + 2 < NIT) load_stage(it + 2, stg2);
        cp_commit();

        const uint32_t st = sb + (uint32_t)(stg * STAGE_SZ);
#pragma unroll
        for (int t = 0; t < 4; t++) {
            const uint32_t khoff = (uint32_t)(((kh0 + t) & 3) * 32);
            uint32_t a[2][4], b[4][4];
#pragma unroll
            for (int ms = 0; ms < 2; ms++)
                LDSM4(a[ms], st + aLane + (uint32_t)(ms * 16 * ROWB) + khoff);
#pragma unroll
            for (int p = 0; p < 4; p++)
                LDSM4(b[p], st + bLane + (uint32_t)(p * 16 * ROWB) + khoff);
#pragma unroll
            for (int ms = 0; ms < 2; ms++) {
#pragma unroll
                for (int p = 0; p < 4; p++) {
                    mma16816(acc + (ms * 8 + 2 * p) * 4,     a[ms], b[p][0], b[p][1]);
                    mma16816(acc + (ms * 8 + 2 * p + 1) * 4, a[ms], b[p][2], b[p][3]);
                }
            }
        }
        stg = (stg + 1 == STAGES) ? 0 : stg + 1;
    }

    // ---- epilogue: add bias, store fp32 ----
    const int rbase = m0 + warp_m * 32 + (lane >> 2);
    const int cbase = n0 + warp_n * 64 + (lane & 3) * 2;
#pragma unroll
    for (int ms = 0; ms < 2; ms++) {
#pragma unroll
        for (int ns = 0; ns < 8; ns++) {
            const float* c = acc + (ms * 8 + ns) * 4;
            const int col = cbase + ns * 8;
            const float2 bb = *reinterpret_cast<const float2*>(bias + col);
            const int r0 = rbase + ms * 16;
            float2 o0 = { c[0] + bb.x, c[1] + bb.y };
            float2 o1 = { c[2] + bb.x, c[3] + bb.y };
            *reinterpret_cast<float2*>(out + (size_t)r0 * OUTF + col) = o0;
            *reinterpret_cast<float2*>(out + (size_t)(r0 + 8) * OUTF + col) = o1;
        }
    }
}

// ---------------- launch -----------------------------------------------------
extern "C" void kernel_launch(void* const* d_in, const int* in_sizes, int n_in,
                              void* d_out, int out_size)
{
    (void)in_sizes; (void)n_in; (void)out_size;
    const float* x        = (const float*)d_in[0];
    const float* ln_gamma = (const float*)d_in[1];
    const float* ln_beta  = (const float*)d_in[2];
    const float* spline_w = (const float*)d_in[3];
    const float* base_w   = (const float*)d_in[4];
    const float* base_b   = (const float*)d_in[5];
    float* out = (float*)d_out;

    cudaFuncSetAttribute(gemm_kernel, cudaFuncAttributeMaxDynamicSharedMemorySize,
                         SMEM_BYTES);

    prep_kernel<<<OUTF + NROWS, 256>>>(spline_w, base_w, x, ln_gamma, ln_beta);
    gemm_kernel<<<dim3(8, 64), NTHR, SMEM_BYTES>>>(base_b, out);
}

// round 11
// speedup vs baseline: 1.0684x; 1.0215x over previous
#include <cuda_runtime.h>
#include <cuda_fp16.h>
#include <cstdint>
#include <cstddef>

#define NROWS  8192
#define INF    1024
#define OUTF   1024
#define KDIM   9216
#define KSTEP  64
#define NIT    144          // KDIM / 64
#define STAGES 3
#define ROWB   144          // 128 data bytes + 16 pad
#define A_SZ   (128 * ROWB)         // 18432
#define B_SZ   (128 * ROWB)         // 18432
#define STAGE_SZ (A_SZ + B_SZ)      // 36864
#define SMEM_BYTES (STAGES * STAGE_SZ)   // 110592
#define NTHR   512

// ---------------- scratch (device globals) ----------------------------------
__device__ __align__(1024) __half g_G[(size_t)NROWS * KDIM];
__device__ __align__(1024) __half g_W[(size_t)OUTF * KDIM];

// ---------------- helpers ----------------------------------------------------
static __device__ __forceinline__ uint32_t smem_u32(const void* p) {
    uint32_t a;
    asm("{ .reg .u64 t; cvta.to.shared.u64 t, %1; cvt.u32.u64 %0, t; }"
        : "=r"(a) : "l"(p));
    return a;
}
static __device__ __forceinline__ void cp16(uint32_t s, const void* g) {
    asm volatile("cp.async.cg.shared.global [%0], [%1], 16;" :: "r"(s), "l"(g));
}
static __device__ __forceinline__ void cp_commit() {
    asm volatile("cp.async.commit_group;" ::: "memory");
}
static __device__ __forceinline__ void cp_wait1() {
    asm volatile("cp.async.wait_group 1;" ::: "memory");
}
#define LDSM4(r, adr) \
    asm volatile("ldmatrix.sync.aligned.m8n8.x4.shared.b16 {%0,%1,%2,%3}, [%4];" \
                 : "=r"((r)[0]), "=r"((r)[1]), "=r"((r)[2]), "=r"((r)[3]) \
                 : "r"(adr))
static __device__ __forceinline__ void mma16816(
    float* c, const uint32_t* a, uint32_t b0, uint32_t b1)
{
    asm volatile(
        "mma.sync.aligned.m16n8k16.row.col.f32.f16.f16.f32 "
        "{%0,%1,%2,%3}, {%4,%5,%6,%7}, {%8,%9}, {%0,%1,%2,%3};"
        : "+f"(c[0]), "+f"(c[1]), "+f"(c[2]), "+f"(c[3])
        : "r"(a[0]), "r"(a[1]), "r"(a[2]), "r"(a[3]), "r"(b0), "r"(b1));
}
static __device__ __forceinline__ uint32_t pack_h2(float a, float b) {
    __half2 t = __floats2half2_rn(a, b);
    return *reinterpret_cast<uint32_t*>(&t);
}

// ---------------- kernel 1: prep (W convert + features), merged --------------
__global__ void prep_kernel(const float* __restrict__ spline_w,
                            const float* __restrict__ base_w,
                            const float* __restrict__ x,
                            const float* __restrict__ gamma,
                            const float* __restrict__ beta)
{
    const int tid = threadIdx.x;            // 256 threads

    if (blockIdx.x < OUTF) {
        const int o = blockIdx.x;
        const size_t rb = (size_t)o * KDIM;
        for (int k = tid; k < KDIM; k += 256) {
            float v = (k < 8192) ? spline_w[(size_t)o * 8192 + k]
                                 : base_w[(size_t)o * 1024 + (k - 8192)];
            g_W[rb + k] = __float2half_rn(v);
        }
        return;
    }

    const int row = blockIdx.x - OUTF;
    const int lane = tid & 31, wid = tid >> 5;

    const float4 v = reinterpret_cast<const float4*>(x + (size_t)row * INF)[tid];
    float s  = v.x + v.y + v.z + v.w;
    float sq = v.x * v.x + v.y * v.y + v.z * v.z + v.w * v.w;
#pragma unroll
    for (int o = 16; o > 0; o >>= 1) {
        s  += __shfl_xor_sync(0xFFFFFFFFu, s,  o);
        sq += __shfl_xor_sync(0xFFFFFFFFu, sq, o);
    }
    __shared__ float rs[8], rq[8], s_mu, s_rstd;
    if (lane == 0) { rs[wid] = s; rq[wid] = sq; }
    __syncthreads();
    if (tid == 0) {
        float S = 0.f, Q = 0.f;
#pragma unroll
        for (int i = 0; i < 8; i++) { S += rs[i]; Q += rq[i]; }
        float mu = S * (1.0f / INF);
        float var = Q * (1.0f / INF) - mu * mu;
        s_mu = mu;
        s_rstd = rsqrtf(var + 1e-5f);
    }
    __syncthreads();
    const float mu = s_mu, rstd = s_rstd;

    __half* gh = g_G + (size_t)row * KDIM;
    const float xv4[4] = { v.x, v.y, v.z, v.w };

#pragma unroll
    for (int e = 0; e < 4; e++) {
        const int in = tid * 4 + e;
        const float xv = xv4[e];
        const float xn = (xv - mu) * rstd * gamma[in] + beta[in];
        const float t0 = (xn + 2.0f) * 1.75f;   // (xn - grid_g)/DENOM = t0 - g
        float b[8];
#pragma unroll
        for (int g = 0; g < 8; g++) {
            float d = t0 - (float)g;
            b[g] = __expf(-d * d);
        }
        uint4 H;
        H.x = pack_h2(b[0], b[1]); H.y = pack_h2(b[2], b[3]);
        H.z = pack_h2(b[4], b[5]); H.w = pack_h2(b[6], b[7]);
        *reinterpret_cast<uint4*>(gh + (size_t)in * 8) = H;

        float sl = xv / (1.0f + __expf(-xv));     // silu(x), original x
        gh[8192 + in] = __float2half_rn(sl);
    }
}

// ---------------- kernel 2: mma.sync GEMM  Y = G W^T + b ---------------------
// CTA 128x128, 16 warps of 32x32 (4m x 4n), K-step 64, 3-stage cp.async,
// 2 CTAs / SM (32 warps/SM = 8 per scheduler).
__global__ void __launch_bounds__(NTHR, 2)
gemm_kernel(const float* __restrict__ bias, float* __restrict__ out)
{
    extern __shared__ __align__(128) char smem[];
    const uint32_t sb = smem_u32(smem);
    const int tid  = threadIdx.x;
    const int lane = tid & 31;
    const int wid  = tid >> 5;
    const int warp_m = wid & 3;     // 4 x 32 rows
    const int warp_n = wid >> 2;    // 4 x 32 cols
    const int n0 = blockIdx.x * 128;
    const int m0 = blockIdx.y * 128;

    // ---- cp.async per-thread geometry (16B chunks, 8 per 128B row) ----
    const __half* baseG = g_G;
    const __half* baseW = g_W;
    uint32_t dA[2], gA[2];
#pragma unroll
    for (int j = 0; j < 2; j++) {                 // A: 1024 chunks / 512 thr
        int c = tid + NTHR * j;
        int r = c >> 3, sgs = c & 7;
        dA[j] = (uint32_t)(r * ROWB + sgs * 16);
        gA[j] = (uint32_t)((m0 + r) * KDIM + sgs * 8);
    }
    uint32_t dB[2], gB[2];
#pragma unroll
    for (int j = 0; j < 2; j++) {                 // B: 1024 chunks / 512 thr
        int c = tid + NTHR * j;
        int r = c >> 3, sgs = c & 7;
        dB[j] = (uint32_t)(A_SZ + r * ROWB + sgs * 16);
        gB[j] = (uint32_t)((n0 + r) * KDIM + sgs * 8);
    }

    auto load_stage = [&](int it, int stg) {
        const uint32_t kcol = (uint32_t)it * KSTEP;
        const uint32_t st = sb + (uint32_t)(stg * STAGE_SZ);
#pragma unroll
        for (int j = 0; j < 2; j++) cp16(st + dA[j], baseG + gA[j] + kcol);
#pragma unroll
        for (int j = 0; j < 2; j++) cp16(st + dB[j], baseW + gB[j] + kcol);
    };

    // ---- ldmatrix per-thread lane offsets ----
    const uint32_t aLane = (uint32_t)((warp_m * 32 + ((lane >> 3) & 1) * 8 + (lane & 7)) * ROWB
                                      + (lane >> 4) * 16);
    const uint32_t bLane = (uint32_t)(A_SZ
                                      + (warp_n * 32 + ((lane >> 4) & 1) * 8 + (lane & 7)) * ROWB
                                      + ((lane >> 3) & 1) * 16);

    float acc[32];
#pragma unroll
    for (int i = 0; i < 32; i++) acc[i] = 0.0f;

    // prologue: fill 2 stages
    load_stage(0, 0); cp_commit();
    load_stage(1, 1); cp_commit();

    int stg = 0;
    for (int it = 0; it < NIT; it++) {
        cp_wait1();                 // stage(it) resident
        __syncthreads();
        const int stg2 = (stg + 2 >= STAGES) ? stg - 1 : stg + 2;
        if (it + 2 < NIT) load_stage(it + 2, stg2);
        cp_commit();

        const uint32_t st = sb + (uint32_t)(stg * STAGE_SZ);
#pragma unroll
        for (int kh = 0; kh < 4; kh++) {
            const uint32_t khoff = (uint32_t)(kh * 32);
            uint32_t a[2][4], b[2][4];
#pragma unroll
            for (int ms = 0; ms < 2; ms++)
                LDSM4(a[ms], st + aLane + (uint32_t)(ms * 16 * ROWB) + khoff);
#pragma unroll
            for (int p = 0; p < 2; p++)
                LDSM4(b[p], st + bLane + (uint32_t)(p * 16 * ROWB) + khoff);
#pragma unroll
            for (int ms = 0; ms < 2; ms++) {
#pragma unroll
                for (int p = 0; p < 2; p++) {
                    mma16816(acc + (ms * 4 + 2 * p) * 4,     a[ms], b[p][0], b[p][1]);
                    mma16816(acc + (ms * 4 + 2 * p + 1) * 4, a[ms], b[p][2], b[p][3]);
                }
            }
        }
        stg = (stg + 1 == STAGES) ? 0 : stg + 1;
    }

    // ---- epilogue: add bias, store fp32 ----
    const int rbase = m0 + warp_m * 32 + (lane >> 2);
    const int cbase = n0 + warp_n * 32 + (lane & 3) * 2;
#pragma unroll
    for (int ms = 0; ms < 2; ms++) {
#pragma unroll
        for (int ns = 0; ns < 4; ns++) {
            const float* c = acc + (ms * 4 + ns) * 4;
            const int col = cbase + ns * 8;
            const float2 bb = *reinterpret_cast<const float2*>(bias + col);
            const int r0 = rbase + ms * 16;
            float2 o0 = { c[0] + bb.x, c[1] + bb.y };
            float2 o1 = { c[2] + bb.x, c[3] + bb.y };
            *reinterpret_cast<float2*>(out + (size_t)r0 * OUTF + col) = o0;
            *reinterpret_cast<float2*>(out + (size_t)(r0 + 8) * OUTF + col) = o1;
        }
    }
}

// ---------------- launch -----------------------------------------------------
extern "C" void kernel_launch(void* const* d_in, const int* in_sizes, int n_in,
                              void* d_out, int out_size)
{
    (void)in_sizes; (void)n_in; (void)out_size;
    const float* x        = (const float*)d_in[0];
    const float* ln_gamma = (const float*)d_in[1];
    const float* ln_beta  = (const float*)d_in[2];
    const float* spline_w = (const float*)d_in[3];
    const float* base_w   = (const float*)d_in[4];
    const float* base_b   = (const float*)d_in[5];
    float* out = (float*)d_out;

    cudaFuncSetAttribute(gemm_kernel, cudaFuncAttributeMaxDynamicSharedMemorySize,
                         SMEM_BYTES);

    prep_kernel<<<OUTF + NROWS, 256>>>(spline_w, base_w, x, ln_gamma, ln_beta);
    gemm_kernel<<<dim3(8, 64), NTHR, SMEM_BYTES>>>(base_b, out);
}

// round 12
// speedup vs baseline: 1.1278x; 1.0556x over previous
#include <cuda_runtime.h>
#include <cuda_fp16.h>
#include <cstdint>
#include <cstddef>

#define NROWS  8192
#define INF    1024
#define OUTF   1024
#define KDIM   9216
#define KSTEP  64
#define NIT    144          // KDIM / 64
#define STAGES 3
#define ROWB   144          // 128 data bytes + 16 pad
#define A_SZ   (128 * ROWB)         // 18432
#define B_SZ   (128 * ROWB)         // 18432
#define STAGE_SZ (A_SZ + B_SZ)      // 36864
#define BAR_OFF (STAGES * STAGE_SZ) // barriers after stages
#define SMEM_BYTES (BAR_OFF + 64)   // 110656
#define NTHR   256

// ---------------- scratch (device globals) ----------------------------------
__device__ __align__(1024) __half g_G[(size_t)NROWS * KDIM];
__device__ __align__(1024) __half g_W[(size_t)OUTF * KDIM];

// ---------------- helpers ----------------------------------------------------
static __device__ __forceinline__ uint32_t smem_u32(const void* p) {
    uint32_t a;
    asm("{ .reg .u64 t; cvta.to.shared.u64 t, %1; cvt.u32.u64 %0, t; }"
        : "=r"(a) : "l"(p));
    return a;
}
static __device__ __forceinline__ void cp16(uint32_t s, const void* g) {
    asm volatile("cp.async.cg.shared.global [%0], [%1], 16;" :: "r"(s), "l"(g));
}
static __device__ __forceinline__ void cp_commit() {
    asm volatile("cp.async.commit_group;" ::: "memory");
}
static __device__ __forceinline__ void cp_wait2() {
    asm volatile("cp.async.wait_group 2;" ::: "memory");
}
static __device__ __forceinline__ void mbar_init(uint32_t m, uint32_t c) {
    asm volatile("mbarrier.init.shared.b64 [%0], %1;" :: "r"(m), "r"(c) : "memory");
}
static __device__ __forceinline__ void mbar_arrive(uint32_t m) {
    asm volatile("mbarrier.arrive.shared.b64 _, [%0];" :: "r"(m) : "memory");
}
static __device__ __forceinline__ void mbar_wait(uint32_t m, uint32_t ph) {
    asm volatile(
        "{\n\t.reg .pred P;\n"
        "LW_%=:\n\t"
        "mbarrier.try_wait.parity.shared.b64 P, [%0], %1;\n\t"
        "@P bra LD_%=;\n\t"
        "bra LW_%=;\n"
        "LD_%=:\n\t}"
        :: "r"(m), "r"(ph) : "memory");
}
#define LDSM4(r, adr) \
    asm volatile("ldmatrix.sync.aligned.m8n8.x4.shared.b16 {%0,%1,%2,%3}, [%4];" \
                 : "=r"((r)[0]), "=r"((r)[1]), "=r"((r)[2]), "=r"((r)[3]) \
                 : "r"(adr))
static __device__ __forceinline__ void mma16816(
    float* c, const uint32_t* a, uint32_t b0, uint32_t b1)
{
    asm volatile(
        "mma.sync.aligned.m16n8k16.row.col.f32.f16.f16.f32 "
        "{%0,%1,%2,%3}, {%4,%5,%6,%7}, {%8,%9}, {%0,%1,%2,%3};"
        : "+f"(c[0]), "+f"(c[1]), "+f"(c[2]), "+f"(c[3])
        : "r"(a[0]), "r"(a[1]), "r"(a[2]), "r"(a[3]), "r"(b0), "r"(b1));
}
static __device__ __forceinline__ uint32_t pack_h2(float a, float b) {
    __half2 t = __floats2half2_rn(a, b);
    return *reinterpret_cast<uint32_t*>(&t);
}

// ---------------- kernel 1: prep (W convert + features), merged --------------
__global__ void prep_kernel(const float* __restrict__ spline_w,
                            const float* __restrict__ base_w,
                            const float* __restrict__ x,
                            const float* __restrict__ gamma,
                            const float* __restrict__ beta)
{
    const int tid = threadIdx.x;            // 256 threads

    if (blockIdx.x < OUTF) {
        const int o = blockIdx.x;
        const size_t rb = (size_t)o * KDIM;
        for (int k = tid; k < KDIM; k += 256) {
            float v = (k < 8192) ? spline_w[(size_t)o * 8192 + k]
                                 : base_w[(size_t)o * 1024 + (k - 8192)];
            g_W[rb + k] = __float2half_rn(v);
        }
        return;
    }

    const int row = blockIdx.x - OUTF;
    const int lane = tid & 31, wid = tid >> 5;

    const float4 v = reinterpret_cast<const float4*>(x + (size_t)row * INF)[tid];
    float s  = v.x + v.y + v.z + v.w;
    float sq = v.x * v.x + v.y * v.y + v.z * v.z + v.w * v.w;
#pragma unroll
    for (int o = 16; o > 0; o >>= 1) {
        s  += __shfl_xor_sync(0xFFFFFFFFu, s,  o);
        sq += __shfl_xor_sync(0xFFFFFFFFu, sq, o);
    }
    __shared__ float rs[8], rq[8], s_mu, s_rstd;
    if (lane == 0) { rs[wid] = s; rq[wid] = sq; }
    __syncthreads();
    if (tid == 0) {
        float S = 0.f, Q = 0.f;
#pragma unroll
        for (int i = 0; i < 8; i++) { S += rs[i]; Q += rq[i]; }
        float mu = S * (1.0f / INF);
        float var = Q * (1.0f / INF) - mu * mu;
        s_mu = mu;
        s_rstd = rsqrtf(var + 1e-5f);
    }
    __syncthreads();
    const float mu = s_mu, rstd = s_rstd;

    __half* gh = g_G + (size_t)row * KDIM;
    const float xv4[4] = { v.x, v.y, v.z, v.w };

#pragma unroll
    for (int e = 0; e < 4; e++) {
        const int in = tid * 4 + e;
        const float xv = xv4[e];
        const float xn = (xv - mu) * rstd * gamma[in] + beta[in];
        const float t0 = (xn + 2.0f) * 1.75f;   // (xn - grid_g)/DENOM = t0 - g
        float b[8];
#pragma unroll
        for (int g = 0; g < 8; g++) {
            float d = t0 - (float)g;
            b[g] = __expf(-d * d);
        }
        uint4 H;
        H.x = pack_h2(b[0], b[1]); H.y = pack_h2(b[2], b[3]);
        H.z = pack_h2(b[4], b[5]); H.w = pack_h2(b[6], b[7]);
        *reinterpret_cast<uint4*>(gh + (size_t)in * 8) = H;

        float sl = xv / (1.0f + __expf(-xv));     // silu(x), original x
        gh[8192 + in] = __float2half_rn(sl);
    }
}

// ---------------- kernel 2: mma.sync GEMM  Y = G W^T + b ---------------------
// CTA 128x128, 8 warps of 32x64 (4m x 2n), K-step 64, 3-stage ring with
// per-stage full/empty mbarriers (no in-loop __syncthreads), 2 CTAs / SM.
__global__ void __launch_bounds__(NTHR, 2)
gemm_kernel(const float* __restrict__ bias, float* __restrict__ out)
{
    extern __shared__ __align__(128) char smem[];
    const uint32_t sb = smem_u32(smem);
    const int tid  = threadIdx.x;
    const int lane = tid & 31;
    const int wid  = tid >> 5;
    const int warp_m = wid & 3;     // 4 x 32 rows
    const int warp_n = wid >> 2;    // 2 x 64 cols
    const int n0 = blockIdx.x * 128;
    const int m0 = blockIdx.y * 128;

    const uint32_t fullb  = sb + BAR_OFF;        // full[s]  = fullb + 8*s
    const uint32_t emptyb = sb + BAR_OFF + 24;   // empty[s] = emptyb + 8*s

    if (tid == 0) {
#pragma unroll
        for (int s = 0; s < STAGES; s++) {
            mbar_init(fullb + 8u * s, 8);
            mbar_init(emptyb + 8u * s, 8);
        }
    }
    __syncthreads();    // barrier init visible (outside main loop)

    // ---- cp.async per-thread geometry (16B chunks, 8 per 128B row) ----
    const __half* baseG = g_G;
    const __half* baseW = g_W;
    uint32_t dA[4], gA[4];
#pragma unroll
    for (int j = 0; j < 4; j++) {                 // A: 1024 chunks / 256 thr
        int c = tid + NTHR * j;
        int r = c >> 3, sgs = c & 7;
        dA[j] = (uint32_t)(r * ROWB + sgs * 16);
        gA[j] = (uint32_t)((m0 + r) * KDIM + sgs * 8);
    }
    uint32_t dB[4], gB[4];
#pragma unroll
    for (int j = 0; j < 4; j++) {                 // B: 1024 chunks / 256 thr
        int c = tid + NTHR * j;
        int r = c >> 3, sgs = c & 7;
        dB[j] = (uint32_t)(A_SZ + r * ROWB + sgs * 16);
        gB[j] = (uint32_t)((n0 + r) * KDIM + sgs * 8);
    }

    auto load_stage = [&](int it, int stg) {
        const uint32_t kcol = (uint32_t)it * KSTEP;
        const uint32_t st = sb + (uint32_t)(stg * STAGE_SZ);
#pragma unroll
        for (int j = 0; j < 4; j++) cp16(st + dA[j], baseG + gA[j] + kcol);
#pragma unroll
        for (int j = 0; j < 4; j++) cp16(st + dB[j], baseW + gB[j] + kcol);
    };

    // ---- ldmatrix per-thread lane offsets ----
    const uint32_t aLane = (uint32_t)((warp_m * 32 + ((lane >> 3) & 1) * 8 + (lane & 7)) * ROWB
                                      + (lane >> 4) * 16);
    const uint32_t bLane = (uint32_t)(A_SZ
                                      + (warp_n * 64 + ((lane >> 4) & 1) * 8 + (lane & 7)) * ROWB
                                      + ((lane >> 3) & 1) * 16);

    float acc[64];
#pragma unroll
    for (int i = 0; i < 64; i++) acc[i] = 0.0f;

    // prologue: fill stages 0,1
    load_stage(0, 0); cp_commit();
    load_stage(1, 1); cp_commit();

    int sc = 0, pc = 0;     // consumer stage + phase parity
    int sp = 2, fp = 0;     // producer stage (for it+2) + fill index

    for (int it = 0; it < NIT; it++) {
        // producer: refill stage sp with chunk it+2
        if (it + 2 < NIT) {
            if (fp >= 1) mbar_wait(emptyb + 8u * sp, (uint32_t)((fp - 1) & 1));
            load_stage(it + 2, sp);
        }
        cp_commit();                       // uniform group count
        cp_wait2();                        // own copies for stage sc complete
        __syncwarp();
        if (lane == 0) mbar_arrive(fullb + 8u * sc);
        mbar_wait(fullb + 8u * sc, (uint32_t)pc);

        const uint32_t st = sb + (uint32_t)(sc * STAGE_SZ);
#pragma unroll
        for (int kh = 0; kh < 4; kh++) {
            const uint32_t khoff = (uint32_t)(kh * 32);
            uint32_t a[2][4], b[4][4];
#pragma unroll
            for (int ms = 0; ms < 2; ms++)
                LDSM4(a[ms], st + aLane + (uint32_t)(ms * 16 * ROWB) + khoff);
#pragma unroll
            for (int p = 0; p < 4; p++)
                LDSM4(b[p], st + bLane + (uint32_t)(p * 16 * ROWB) + khoff);
#pragma unroll
            for (int ms = 0; ms < 2; ms++) {
#pragma unroll
                for (int p = 0; p < 4; p++) {
                    mma16816(acc + (ms * 8 + 2 * p) * 4,     a[ms], b[p][0], b[p][1]);
                    mma16816(acc + (ms * 8 + 2 * p + 1) * 4, a[ms], b[p][2], b[p][3]);
                }
            }
        }
        __syncwarp();
        if (lane == 0) mbar_arrive(emptyb + 8u * sc);

        if (++sc == STAGES) { sc = 0; pc ^= 1; }
        if (++sp == STAGES) { sp = 0; fp++; }
    }

    // ---- epilogue: add bias, store fp32 ----
    const int rbase = m0 + warp_m * 32 + (lane >> 2);
    const int cbase = n0 + warp_n * 64 + (lane & 3) * 2;
#pragma unroll
    for (int ms = 0; ms < 2; ms++) {
#pragma unroll
        for (int ns = 0; ns < 8; ns++) {
            const float* c = acc + (ms * 8 + ns) * 4;
            const int col = cbase + ns * 8;
            const float2 bb = *reinterpret_cast<const float2*>(bias + col);
            const int r0 = rbase + ms * 16;
            float2 o0 = { c[0] + bb.x, c[1] + bb.y };
            float2 o1 = { c[2] + bb.x, c[3] + bb.y };
            *reinterpret_cast<float2*>(out + (size_t)r0 * OUTF + col) = o0;
            *reinterpret_cast<float2*>(out + (size_t)(r0 + 8) * OUTF + col) = o1;
        }
    }
}

// ---------------- launch -----------------------------------------------------
extern "C" void kernel_launch(void* const* d_in, const int* in_sizes, int n_in,
                              void* d_out, int out_size)
{
    (void)in_sizes; (void)n_in; (void)out_size;
    const float* x        = (const float*)d_in[0];
    const float* ln_gamma = (const float*)d_in[1];
    const float* ln_beta  = (const float*)d_in[2];
    const float* spline_w = (const float*)d_in[3];
    const float* base_w   = (const float*)d_in[4];
    const float* base_b   = (const float*)d_in[5];
    float* out = (float*)d_out;

    cudaFuncSetAttribute(gemm_kernel, cudaFuncAttributeMaxDynamicSharedMemorySize,
                         SMEM_BYTES);

    prep_kernel<<<OUTF + NROWS, 256>>>(spline_w, base_w, x, ln_gamma, ln_beta);
    gemm_kernel<<<dim3(8, 64), NTHR, SMEM_BYTES>>>(base_b, out);
}